// round 15
// baseline (speedup 1.0000x reference)
#include <cuda_runtime.h>

// Problem constants
#define BB 16
#define GG 32
#define TT 180
#define NN 1024   // H*W
#define FF 1024
#define SCALE 0.04419417382415922f  // 512^-0.5
#define EPSF 1e-6f
#define WPART 32      // weight-reduction blocks (bids 0..31, first-scheduled)

// ---------------- scratch (no allocs allowed) ----------------
__device__ __align__(16) float g_part[WPART * 512];   // partial column sums of wq
__device__ __align__(16) float2 g_pstat[512 * 16];    // per-(b,g)[slot] (sum, sumsq)
__device__ __align__(16) float g_wa[512];             // wqs[c]*gamma[c]
__device__ __align__(16) float g_wg[32];              // per-group sums of wa
__device__ __align__(16) float g_Wsum[512];           // row sums of wo
__device__ float g_const1;                            // sum(wqs*beta) + sum(bq)
__device__ __align__(16) float g_P[BB * GG * NN];     // 2MB weighted group partials
__device__ __align__(16) float g_k[BB * FF];
__device__ __align__(16) float g_v[BB * FF];
__device__ int g_c1 = 0;      // WEIGHT-block ticket only (32 atomics)
__device__ int g_flag1 = 0;   // wa/wg/const1 ready

// ---------------- kA (R12 form): weights -> flag1 ∥ GEMM ∥ stats then weighted P ----
// grid 672, block 256.
//   bid [0,32):    wq/wo reductions; ticket among 32; last finalizes -> flag1.
//   bid [32,160):  k/v GEMM, 16f x 16b smem tiles.
//   bid [160,672): per-(b,g): pass 1 unweighted sum/sq (overlaps weight phase, no
//                  wait), then short flag1 wait, then weighted P pass from L2.
__global__ void __launch_bounds__(256) kA(
    const float* __restrict__ x, const float* __restrict__ cond,
    const float* __restrict__ gamma, const float* __restrict__ beta,
    const float* __restrict__ wq, const float* __restrict__ bq,
    const float* __restrict__ wk, const float* __restrict__ bk,
    const float* __restrict__ wv, const float* __restrict__ bv,
    const float* __restrict__ wo)
{
    __shared__ float smem[2 * 16 * 181];   // 23.2KB (GEMM tiles); others reuse front
    int t = threadIdx.x;
    int bid = blockIdx.x;
    int w = t >> 5, lane = t & 31;

    if (bid < WPART) {
        // ---- weight reductions: block j owns 16 rows of wq and wo ----
        int j = bid;
        float s0 = 0.f, s1 = 0.f;
#pragma unroll
        for (int r = 0; r < 16; r++) {
            const float* row = wq + (size_t)(j * 16 + r) * 512;
            s0 += row[t];
            s1 += row[t + 256];
        }
        g_part[j * 512 + t] = s0;
        g_part[j * 512 + t + 256] = s1;

        // wo row sums: warp w owns rows j*16+w and j*16+8+w
#pragma unroll
        for (int rr = 0; rr < 2; rr++) {
            const float* rp = wo + (size_t)(j * 16 + rr * 8 + w) * 512;
            float r = 0.f;
#pragma unroll
            for (int i = 0; i < 16; i++) r += rp[lane + 32 * i];
#pragma unroll
            for (int off = 16; off; off >>= 1) r += __shfl_down_sync(0xffffffffu, r, off);
            if (lane == 0) g_Wsum[j * 16 + rr * 8 + w] = r;
        }

        // ---- ticket among the 32 weight blocks only ----
        __syncthreads();
        __threadfence();
        __shared__ int isLast;
        if (t == 0) isLast = (atomicAdd(&g_c1, 1) == WPART - 1);
        __syncthreads();
        if (!isLast) return;
        __threadfence();

        // ---- finalize: wqs -> wa, const1, wg; then flag1 ----
        float wqs0 = 0.f, wqs1 = 0.f;
#pragma unroll 8
        for (int jj = 0; jj < WPART; jj++) {
            wqs0 += g_part[jj * 512 + t];
            wqs1 += g_part[jj * 512 + t + 256];
        }
        float wa0 = wqs0 * gamma[t];
        float wa1 = wqs1 * gamma[t + 256];
        g_wa[t] = wa0;
        g_wa[t + 256] = wa1;

        smem[t] = wqs0 * beta[t] + bq[t] + wqs1 * beta[t + 256] + bq[t + 256];
        __syncthreads();
        for (int st = 128; st; st >>= 1) {
            if (t < st) smem[t] += smem[t + st];
            __syncthreads();
        }
        if (t == 0) { g_const1 = smem[0]; g_c1 = 0; }  // reset ticket for replay

        float wg0 = wa0, wg1 = wa1;
#pragma unroll
        for (int off = 8; off; off >>= 1) {
            wg0 += __shfl_down_sync(0xffffffffu, wg0, off, 16);
            wg1 += __shfl_down_sync(0xffffffffu, wg1, off, 16);
        }
        if ((t & 15) == 0) {
            g_wg[t >> 4] = wg0;
            g_wg[16 + (t >> 4)] = wg1;
        }
        __syncthreads();
        __threadfence();
        if (t == 0) *(volatile int*)&g_flag1 = 1;
        return;
    }

    if (bid < 160) {
        // ---- k/v GEMM: 16 f x 16 b per block ----
        int bx = bid - 32;                // 0..127
        int mat = bx >> 6;                // 0 = k, 1 = v
        int ft = bx & 63;                 // f-tile of 16
        const float* W    = mat ? wv : wk;
        const float* bias = mat ? bv : bk;
        float* o          = mat ? g_v : g_k;

        float (*sw)[181] = (float (*)[181])smem;
        float (*sc)[181] = (float (*)[181])(smem + 16 * 181);
        int f0 = ft * 16;
        for (int i = t; i < 16 * 180; i += 256) {
            int r = i / 180, cc2 = i - r * 180;
            sw[r][cc2] = W[(size_t)(f0 + r) * TT + cc2];
            sc[r][cc2] = cond[r * TT + cc2];
        }
        __syncthreads();

        int fo = t & 15, bb = t >> 4;
        float acc = 0.f;
#pragma unroll 4
        for (int k = 0; k < TT; k++) acc += sw[fo][k] * sc[bb][k];
        o[bb * FF + f0 + fo] = acc + bias[f0 + fo];
        return;
    }

    // ---- stats + weighted P for (b,g) = bid-160 ----
    int bg = bid - 160;
    int g = bg & 31;
    const float4* xs = (const float4*)x + (size_t)bg * 16 * 256;

    // pass 1: unweighted sum/sq, warp w owns channels 2w, 2w+1 (no wait, no barriers)
#pragma unroll
    for (int i = 0; i < 2; i++) {
        int cl = w * 2 + i;                        // channel within group
        const float4* xp = xs + cl * 256;
        float sum = 0.f, sq = 0.f;
#pragma unroll
        for (int j = 0; j < 8; j++) {
            float4 v = xp[lane + 32 * j];
            sum += v.x + v.y + v.z + v.w;
            sq += v.x * v.x + v.y * v.y + v.z * v.z + v.w * v.w;
        }
#pragma unroll
        for (int off = 16; off; off >>= 1) {
            sum += __shfl_xor_sync(0xffffffffu, sum, off);
            sq  += __shfl_xor_sync(0xffffffffu, sq, off);
        }
        if (lane == 0) g_pstat[bg * 16 + cl] = make_float2(sum, sq);
    }

    // short wait for weights (weight blocks scheduled first; bounded)
    if (t == 0) { while (*(volatile int*)&g_flag1 == 0) __nanosleep(32); }
    __syncthreads();
    __threadfence();

    // pass 2: weighted P over the same (L2-hot) tile; thread t = float4 column
    float4 p = make_float4(0.f, 0.f, 0.f, 0.f);
#pragma unroll
    for (int c = 0; c < 16; c++) {
        float wv_ = g_wa[g * 16 + c];
        float4 v = xs[c * 256 + t];
        p.x += wv_ * v.x; p.y += wv_ * v.y; p.z += wv_ * v.z; p.w += wv_ * v.w;
    }
    ((float4*)g_P)[bg * 256 + t] = p;
}

// ---------------- kE: rs/d + S-from-P + softmax + output stream, fused ----------
// grid 512 (b = blk>>5, 32-n chunk ch = blk&31), block 256 (8 warps).
// __launch_bounds__(256, 6) caps regs at ~42 -> 6 blocks/SM (fixes the occ=33% of R14).
__global__ void __launch_bounds__(256, 6) kE(
    const float* __restrict__ x, const float* __restrict__ bo,
    float* __restrict__ out)
{
    __shared__ float sk[1024], sv[1024], sS[32], sA[32];
    __shared__ float srs[32], sd[1];
    int bid = blockIdx.x;
    int b  = bid >> 5;
    int ch = bid & 31;
    int n0 = ch * 32;
    int t = threadIdx.x;
    int w = t >> 5, lane = t & 31;

    if (bid == 0 && t == 0) g_flag1 = 0;   // reset for next replay (kA done by now)

    ((float4*)sk)[t] = ((const float4*)(g_k + b * FF))[t];
    ((float4*)sv)[t] = ((const float4*)(g_v + b * FF))[t];
    if (w == 7) {
        // lane = group g: mean/var/rs from 16 channel partials
        float sum = 0.f, sq = 0.f;
#pragma unroll
        for (int s = 0; s < 16; s++) {
            float2 p = g_pstat[(b * 32 + lane) * 16 + s];
            sum += p.x; sq += p.y;
        }
        const float inv = 1.f / 16384.f;
        float mean = sum * inv;
        float var = sq * inv - mean * mean;
        float rs = rsqrtf(var + EPSF);
        srs[lane] = rs;
        float v = mean * rs * g_wg[lane];
#pragma unroll
        for (int off = 16; off; off >>= 1) v += __shfl_down_sync(0xffffffffu, v, off);
        if (lane == 0) sd[0] = g_const1 - v;
    }
    __syncthreads();
    float d = sd[0];

    // ---- S from P: 4 n per warp, lane = group ----
#pragma unroll
    for (int i = 0; i < 4; i++) {
        int n = w * 4 + i;
        float ps = srs[lane] * g_P[((size_t)b * 32 + lane) * NN + n0 + n];
#pragma unroll
        for (int off = 16; off; off >>= 1) ps += __shfl_xor_sync(0xffffffffu, ps, off);
        if (lane == 0) sS[n] = (ps + d) * SCALE;
    }
    __syncthreads();

    // ---- softmax-weighted average (no max-sub: logits tiny by construction) ----
#pragma unroll
    for (int i = 0; i < 4; i++) {
        int n = w * 4 + i;
        float s = sS[n];
        float l = 0.f, acc = 0.f;
#pragma unroll 4
        for (int j = 0; j < 8; j++) {
            float4 k4v = ((float4*)sk)[j * 32 + lane];
            float4 v4  = ((float4*)sv)[j * 32 + lane];
            float e0 = __expf(s * k4v.x), e1 = __expf(s * k4v.y);
            float e2 = __expf(s * k4v.z), e3 = __expf(s * k4v.w);
            l += e0 + e1 + e2 + e3;
            acc += v4.x * e0 + v4.y * e1 + v4.z * e2 + v4.w * e3;
        }
#pragma unroll
        for (int off = 16; off; off >>= 1) {
            l   += __shfl_xor_sync(0xffffffffu, l, off);
            acc += __shfl_xor_sync(0xffffffffu, acc, off);
        }
        if (lane == 0) sA[n] = acc / l;
    }
    __syncthreads();

    // ---- output stream: out[b, :, n0:n0+32] = x + Wsum[c]*A[n] + bo[c] ----
    // __stcs: out is write-once, evict-first keeps x resident in L2.
    int f4 = t & 7, c0 = t >> 3;
    const float4* xp = (const float4*)x + ((size_t)b * 512) * 256 + ch * 8;
    float4*       op = (float4*)out     + ((size_t)b * 512) * 256 + ch * 8;
    float4 a = ((float4*)sA)[f4];
#pragma unroll 4
    for (int it = 0; it < 16; it++) {
        int c = c0 + 32 * it;
        float wv_ = g_Wsum[c];
        float bb = bo[c];
        float4 xv = xp[(size_t)c * 256 + f4];
        float4 o;
        o.x = xv.x + wv_ * a.x + bb;
        o.y = xv.y + wv_ * a.y + bb;
        o.z = xv.z + wv_ * a.z + bb;
        o.w = xv.w + wv_ * a.w + bb;
        __stcs(&op[(size_t)c * 256 + f4], o);
    }
}

extern "C" void kernel_launch(void* const* d_in, const int* in_sizes, int n_in,
                              void* d_out, int out_size) {
    const float* x     = (const float*)d_in[0];
    const float* cond  = (const float*)d_in[1];
    const float* gamma = (const float*)d_in[2];
    const float* beta  = (const float*)d_in[3];
    const float* wq    = (const float*)d_in[4];
    const float* bq    = (const float*)d_in[5];
    const float* wk    = (const float*)d_in[6];
    const float* bk    = (const float*)d_in[7];
    const float* wv    = (const float*)d_in[8];
    const float* bv    = (const float*)d_in[9];
    const float* wo    = (const float*)d_in[10];
    const float* bo    = (const float*)d_in[11];
    float* out = (float*)d_out;

    kA<<<672, 256>>>(x, cond, gamma, beta, wq, bq, wk, bk, wv, bv, wo);
    kE<<<512, 256>>>(x, bo, out);
}

// round 16
// speedup vs baseline: 1.2963x; 1.2963x over previous
#include <cuda_runtime.h>

// Problem constants
#define BB 16
#define GG 32
#define TT 180
#define NN 1024   // H*W
#define FF 1024
#define SCALE 0.04419417382415922f  // 512^-0.5
#define EPSF 1e-6f
#define WPART 32      // weight-reduction blocks (bids 0..31, first-scheduled)

// ---------------- scratch (no allocs allowed) ----------------
__device__ __align__(16) float g_part[WPART * 512];   // partial column sums of wq
__device__ __align__(16) float2 g_pstat[512 * 16];    // per-(b,g)[slot] (sum, sumsq)
__device__ __align__(16) float g_wa[512];             // wqs[c]*gamma[c]
__device__ __align__(16) float g_wg[32];              // per-group sums of wa
__device__ __align__(16) float g_Wsum[512];           // row sums of wo
__device__ float g_const1;                            // sum(wqs*beta) + sum(bq)
__device__ __align__(16) float g_P[BB * GG * NN];     // 2MB weighted group partials
__device__ __align__(16) float g_k[BB * FF];
__device__ __align__(16) float g_v[BB * FF];
__device__ __align__(16) float g_A[BB * NN];
__device__ int g_c1 = 0;      // WEIGHT-block ticket only (32 atomics)
__device__ int g_flag1 = 0;   // wa/wg/const1 ready

// ---------------- kA: weights -> flag1 ∥ GEMM ∥ stats then weighted P ----------------
// grid 672, block 256.  (R12 form, measured 16.4us)
//   bid [0,32):    wq/wo reductions; ticket among 32; last finalizes -> flag1.
//   bid [32,160):  k/v GEMM, 16f x 16b smem tiles.
//   bid [160,672): per-(b,g): pass 1 unweighted sum/sq (overlaps weight phase, no
//                  wait), then short flag1 wait, then weighted P pass from L2.
__global__ void __launch_bounds__(256) kA(
    const float* __restrict__ x, const float* __restrict__ cond,
    const float* __restrict__ gamma, const float* __restrict__ beta,
    const float* __restrict__ wq, const float* __restrict__ bq,
    const float* __restrict__ wk, const float* __restrict__ bk,
    const float* __restrict__ wv, const float* __restrict__ bv,
    const float* __restrict__ wo)
{
    __shared__ float smem[2 * 16 * 181];   // 23.2KB (GEMM tiles); others reuse front
    int t = threadIdx.x;
    int bid = blockIdx.x;
    int w = t >> 5, lane = t & 31;

    if (bid < WPART) {
        // ---- weight reductions: block j owns 16 rows of wq and wo ----
        int j = bid;
        float s0 = 0.f, s1 = 0.f;
#pragma unroll
        for (int r = 0; r < 16; r++) {
            const float* row = wq + (size_t)(j * 16 + r) * 512;
            s0 += row[t];
            s1 += row[t + 256];
        }
        g_part[j * 512 + t] = s0;
        g_part[j * 512 + t + 256] = s1;

        // wo row sums: warp w owns rows j*16+w and j*16+8+w
#pragma unroll
        for (int rr = 0; rr < 2; rr++) {
            const float* rp = wo + (size_t)(j * 16 + rr * 8 + w) * 512;
            float r = 0.f;
#pragma unroll
            for (int i = 0; i < 16; i++) r += rp[lane + 32 * i];
#pragma unroll
            for (int off = 16; off; off >>= 1) r += __shfl_down_sync(0xffffffffu, r, off);
            if (lane == 0) g_Wsum[j * 16 + rr * 8 + w] = r;
        }

        // ---- ticket among the 32 weight blocks only ----
        __syncthreads();
        __threadfence();
        __shared__ int isLast;
        if (t == 0) isLast = (atomicAdd(&g_c1, 1) == WPART - 1);
        __syncthreads();
        if (!isLast) return;
        __threadfence();

        // ---- finalize: wqs -> wa, const1, wg; then flag1 ----
        float wqs0 = 0.f, wqs1 = 0.f;
#pragma unroll 8
        for (int jj = 0; jj < WPART; jj++) {
            wqs0 += g_part[jj * 512 + t];
            wqs1 += g_part[jj * 512 + t + 256];
        }
        float wa0 = wqs0 * gamma[t];
        float wa1 = wqs1 * gamma[t + 256];
        g_wa[t] = wa0;
        g_wa[t + 256] = wa1;

        smem[t] = wqs0 * beta[t] + bq[t] + wqs1 * beta[t + 256] + bq[t + 256];
        __syncthreads();
        for (int st = 128; st; st >>= 1) {
            if (t < st) smem[t] += smem[t + st];
            __syncthreads();
        }
        if (t == 0) { g_const1 = smem[0]; g_c1 = 0; }  // reset ticket for replay

        float wg0 = wa0, wg1 = wa1;
#pragma unroll
        for (int off = 8; off; off >>= 1) {
            wg0 += __shfl_down_sync(0xffffffffu, wg0, off, 16);
            wg1 += __shfl_down_sync(0xffffffffu, wg1, off, 16);
        }
        if ((t & 15) == 0) {
            g_wg[t >> 4] = wg0;
            g_wg[16 + (t >> 4)] = wg1;
        }
        __syncthreads();
        __threadfence();
        if (t == 0) *(volatile int*)&g_flag1 = 1;
        return;
    }

    if (bid < 160) {
        // ---- k/v GEMM: 16 f x 16 b per block ----
        int bx = bid - 32;                // 0..127
        int mat = bx >> 6;                // 0 = k, 1 = v
        int ft = bx & 63;                 // f-tile of 16
        const float* W    = mat ? wv : wk;
        const float* bias = mat ? bv : bk;
        float* o          = mat ? g_v : g_k;

        float (*sw)[181] = (float (*)[181])smem;
        float (*sc)[181] = (float (*)[181])(smem + 16 * 181);
        int f0 = ft * 16;
        for (int i = t; i < 16 * 180; i += 256) {
            int r = i / 180, cc2 = i - r * 180;
            sw[r][cc2] = W[(size_t)(f0 + r) * TT + cc2];
            sc[r][cc2] = cond[r * TT + cc2];
        }
        __syncthreads();

        int fo = t & 15, bb = t >> 4;
        float acc = 0.f;
#pragma unroll 4
        for (int k = 0; k < TT; k++) acc += sw[fo][k] * sc[bb][k];
        o[bb * FF + f0 + fo] = acc + bias[f0 + fo];
        return;
    }

    // ---- stats + weighted P for (b,g) = bid-160 ----
    int bg = bid - 160;
    int g = bg & 31;
    const float4* xs = (const float4*)x + (size_t)bg * 16 * 256;

    // pass 1: unweighted sum/sq, warp w owns channels 2w, 2w+1 (no wait, no barriers)
#pragma unroll
    for (int i = 0; i < 2; i++) {
        int cl = w * 2 + i;                        // channel within group
        const float4* xp = xs + cl * 256;
        float sum = 0.f, sq = 0.f;
#pragma unroll
        for (int j = 0; j < 8; j++) {
            float4 v = xp[lane + 32 * j];
            sum += v.x + v.y + v.z + v.w;
            sq += v.x * v.x + v.y * v.y + v.z * v.z + v.w * v.w;
        }
#pragma unroll
        for (int off = 16; off; off >>= 1) {
            sum += __shfl_xor_sync(0xffffffffu, sum, off);
            sq  += __shfl_xor_sync(0xffffffffu, sq, off);
        }
        if (lane == 0) g_pstat[bg * 16 + cl] = make_float2(sum, sq);
    }

    // short wait for weights (weight blocks scheduled first; bounded)
    if (t == 0) { while (*(volatile int*)&g_flag1 == 0) __nanosleep(32); }
    __syncthreads();
    __threadfence();

    // pass 2: weighted P over the same (L2-hot) tile; thread t = float4 column
    float4 p = make_float4(0.f, 0.f, 0.f, 0.f);
#pragma unroll
    for (int c = 0; c < 16; c++) {
        float wv_ = g_wa[g * 16 + c];
        float4 v = xs[c * 256 + t];
        p.x += wv_ * v.x; p.y += wv_ * v.y; p.z += wv_ * v.z; p.w += wv_ * v.w;
    }
    ((float4*)g_P)[bg * 256 + t] = p;
}

// ---------------- kC: rs/d finalize + S from P + softmax-weighted avg -> g_A -----
// grid 256 (b = blk>>4, 64-n chunk = blk&15), block 512 (16 warps).  (R12 form)
__global__ void __launch_bounds__(512) kC(const float* __restrict__ x)
{
    __shared__ float sk[1024], sv[1024], sS[64];
    __shared__ float srs[32], sd[1];
    int bid = blockIdx.x;
    int b  = bid >> 4;
    int nc = bid & 15;
    int n0 = nc * 64;
    int t = threadIdx.x;
    int w = t >> 5, lane = t & 31;

    if (bid == 0 && t == 0) g_flag1 = 0;   // reset for next replay (kA done by now)

    if (t < 256) ((float4*)sk)[t] = ((const float4*)(g_k + b * FF))[t];
    else         ((float4*)sv)[t - 256] = ((const float4*)(g_v + b * FF))[t - 256];
    if (w == 15) {
        // lane = group g: mean/var/rs from 16 channel partials
        float sum = 0.f, sq = 0.f;
#pragma unroll
        for (int s = 0; s < 16; s++) {
            float2 p = g_pstat[(b * 32 + lane) * 16 + s];
            sum += p.x; sq += p.y;
        }
        const float inv = 1.f / 16384.f;
        float mean = sum * inv;
        float var = sq * inv - mean * mean;
        float rs = rsqrtf(var + EPSF);
        srs[lane] = rs;
        float v = mean * rs * g_wg[lane];
#pragma unroll
        for (int off = 16; off; off >>= 1) v += __shfl_down_sync(0xffffffffu, v, off);
        if (lane == 0) sd[0] = g_const1 - v;
    }
    __syncthreads();
    float d = sd[0];

    // ---- S from P: 4 n per warp, lane = group ----
#pragma unroll
    for (int i = 0; i < 4; i++) {
        int n = w * 4 + i;
        float ps = srs[lane] * g_P[((size_t)(b * 32 + lane)) * NN + n0 + n];
#pragma unroll
        for (int off = 16; off; off >>= 1) ps += __shfl_xor_sync(0xffffffffu, ps, off);
        if (lane == 0) sS[n] = (ps + d) * SCALE;
    }
    __syncthreads();

    // ---- softmax-weighted average (no max-sub: logits tiny by construction) ----
#pragma unroll
    for (int i = 0; i < 4; i++) {
        int n = w * 4 + i;
        float s = sS[n];
        float l = 0.f, acc = 0.f;
#pragma unroll
        for (int j = 0; j < 8; j++) {
            float4 k4v = ((float4*)sk)[j * 32 + lane];
            float4 v4  = ((float4*)sv)[j * 32 + lane];
            float e0 = __expf(s * k4v.x), e1 = __expf(s * k4v.y);
            float e2 = __expf(s * k4v.z), e3 = __expf(s * k4v.w);
            l += e0 + e1 + e2 + e3;
            acc += v4.x * e0 + v4.y * e1 + v4.z * e2 + v4.w * e3;
        }
#pragma unroll
        for (int off = 16; off; off >>= 1) {
            l   += __shfl_xor_sync(0xffffffffu, l, off);
            acc += __shfl_xor_sync(0xffffffffu, acc, off);
        }
        if (lane == 0) g_A[b * NN + n0 + n] = acc / l;
    }
}

// ---------------- kD: out = x + Wsum[c]*A[b,n] + bo[c], pure linear stream -------
// float4 over n. 8192 blocks x 256. __stcs on out (write-once) keeps x L2-resident.
__global__ void __launch_bounds__(256) kD(
    const float* __restrict__ x, const float* __restrict__ bo,
    float* __restrict__ out)
{
    size_t i = (size_t)blockIdx.x * 256 + threadIdx.x;  // float4 index
    int n4 = (int)(i & 255);
    int c = (int)((i >> 8) & 511);
    int b = (int)(i >> 17);
    float4 xv = ((const float4*)x)[i];
    float4 av = ((const float4*)g_A)[b * 256 + n4];
    float wv = g_Wsum[c];
    float bb = bo[c];
    float4 o;
    o.x = xv.x + wv * av.x + bb;
    o.y = xv.y + wv * av.y + bb;
    o.z = xv.z + wv * av.z + bb;
    o.w = xv.w + wv * av.w + bb;
    __stcs(&((float4*)out)[i], o);
}

extern "C" void kernel_launch(void* const* d_in, const int* in_sizes, int n_in,
                              void* d_out, int out_size) {
    const float* x     = (const float*)d_in[0];
    const float* cond  = (const float*)d_in[1];
    const float* gamma = (const float*)d_in[2];
    const float* beta  = (const float*)d_in[3];
    const float* wq    = (const float*)d_in[4];
    const float* bq    = (const float*)d_in[5];
    const float* wk    = (const float*)d_in[6];
    const float* bk    = (const float*)d_in[7];
    const float* wv    = (const float*)d_in[8];
    const float* bv    = (const float*)d_in[9];
    const float* wo    = (const float*)d_in[10];
    const float* bo    = (const float*)d_in[11];
    float* out = (float*)d_out;

    kA<<<672, 256>>>(x, cond, gamma, beta, wq, bq, wk, bk, wv, bv, wo);
    kC<<<256, 512>>>(x);
    kD<<<8192, 256>>>(x, bo, out);
}